// round 1
// baseline (speedup 1.0000x reference)
#include <cuda_runtime.h>
#include <cuda_bf16.h>
#include <cstddef>

// ---------------------------------------------------------------------------
// Scratch (device globals; no dynamic allocation allowed)
// ---------------------------------------------------------------------------
#define N_OBJ 4096

__device__ float g_em512[N_OBJ * 512];     // relu(all_embeds @ semantic_W^T + b)
__device__ float g_t[N_OBJ * 1024];        // x @ W buffers (t1 / t2)
__device__ float g_h[N_OBJ * 1024];        // relu(adj @ t + b) buffers (h1 / h2)
__device__ float g_scores512[512];
__device__ float g_r[1024];                // scores512 @ gc1_W[:512,:]
__device__ float g_v[N_OBJ];               // h2 @ gc3_W
__device__ float g_h3[N_OBJ];              // relu(adj @ v + gc3_b)
__device__ float g_joint[1536];            // [visual | semantic | gcn512]
__device__ float g_x[512];                 // hidden layer output

// ---------------------------------------------------------------------------
// Tiled SGEMM: C[M,N] = A[M,K] * op(B) (+ addvec[n]) (optional ReLU)
//   TRANSB=false : B is [K,N] row-major (ldb = N)
//   TRANSB=true  : B is [N,K] row-major (ldb = K)   (i.e. C = A @ B^T)
// Requires M % 128 == 0, N % 128 == 0 (true for all call sites). K arbitrary.
// ---------------------------------------------------------------------------
#define BM 128
#define BN 128
#define BK 16
#define SPAD 4

template <bool TRANSB>
__global__ __launch_bounds__(256, 2)
void sgemm_kernel(const float* __restrict__ A, const float* __restrict__ B,
                  float* __restrict__ C, int M, int N, int K,
                  const float* __restrict__ addvec, int do_relu)
{
    __shared__ float As[BK][BM + SPAD];
    __shared__ float Bs[BK][BN + SPAD];

    const int tid = threadIdx.x;       // 0..255
    const int tx = tid & 15;           // 0..15 -> n
    const int ty = tid >> 4;           // 0..15 -> m
    const int m0 = blockIdx.y * BM;
    const int n0 = blockIdx.x * BN;

    float acc[8][8];
#pragma unroll
    for (int i = 0; i < 8; ++i)
#pragma unroll
        for (int j = 0; j < 8; ++j) acc[i][j] = 0.f;

    for (int k0 = 0; k0 < K; k0 += BK) {
        // --- load A tile [BM][BK] -> As[k][m]
#pragma unroll
        for (int j = 0; j < 8; ++j) {
            int l  = tid + j * 256;        // 0..2047
            int mm = l >> 4;               // /BK
            int kk = l & 15;
            int gk = k0 + kk;
            As[kk][mm] = (gk < K) ? A[(size_t)(m0 + mm) * K + gk] : 0.f;
        }
        // --- load B tile -> Bs[k][n]
        if (!TRANSB) {
#pragma unroll
            for (int j = 0; j < 8; ++j) {
                int l  = tid + j * 256;
                int kk = l >> 7;           // /BN
                int nn = l & 127;
                int gk = k0 + kk;
                Bs[kk][nn] = (gk < K) ? B[(size_t)gk * N + (n0 + nn)] : 0.f;
            }
        } else {
#pragma unroll
            for (int j = 0; j < 8; ++j) {
                int l  = tid + j * 256;
                int nn = l >> 4;
                int kk = l & 15;
                int gk = k0 + kk;
                Bs[kk][nn] = (gk < K) ? B[(size_t)(n0 + nn) * K + gk] : 0.f;
            }
        }
        __syncthreads();

#pragma unroll
        for (int kk = 0; kk < BK; ++kk) {
            float ra[8], rb[8];
#pragma unroll
            for (int i = 0; i < 4; ++i) {
                ra[i]     = As[kk][ty * 4 + i];
                ra[4 + i] = As[kk][64 + ty * 4 + i];
                rb[i]     = Bs[kk][tx * 4 + i];
                rb[4 + i] = Bs[kk][64 + tx * 4 + i];
            }
#pragma unroll
            for (int i = 0; i < 8; ++i)
#pragma unroll
                for (int j = 0; j < 8; ++j)
                    acc[i][j] += ra[i] * rb[j];
        }
        __syncthreads();
    }

    // --- epilogue
#pragma unroll
    for (int i = 0; i < 8; ++i) {
        int mm = (i < 4) ? (ty * 4 + i) : (64 + ty * 4 + (i - 4));
#pragma unroll
        for (int j = 0; j < 8; ++j) {
            int nn = (j < 4) ? (tx * 4 + j) : (64 + tx * 4 + (j - 4));
            float v = acc[i][j];
            if (addvec) v += addvec[n0 + nn];
            if (do_relu) v = fmaxf(v, 0.f);
            C[(size_t)(m0 + mm) * N + (n0 + nn)] = v;
        }
    }
}

// ---------------------------------------------------------------------------
// GEMV: out[row] = op( W[row,:K] . x + bias ), one block (256 thr) per row
// ---------------------------------------------------------------------------
__global__ void gemv_kernel(const float* __restrict__ W, const float* __restrict__ x,
                            const float* __restrict__ b, float* __restrict__ out,
                            int K, int do_relu, int scalar_bias)
{
    const int row = blockIdx.x;
    const float* w = W + (size_t)row * K;
    float s = 0.f;
    for (int k = threadIdx.x; k < K; k += 256) s += w[k] * x[k];

    __shared__ float red[256];
    red[threadIdx.x] = s;
    __syncthreads();
#pragma unroll
    for (int off = 128; off > 0; off >>= 1) {
        if (threadIdx.x < off) red[threadIdx.x] += red[threadIdx.x + off];
        __syncthreads();
    }
    if (threadIdx.x == 0) {
        float v = red[0];
        if (b) v += scalar_bias ? b[0] : b[row];
        if (do_relu) v = fmaxf(v, 0.f);
        out[row] = v;
    }
}

// out[n] = sum_{k<K} x[k] * W[k*ldw + n], n < N  (x^T @ W, coalesced over n)
__global__ void gemv_xtw_kernel(const float* __restrict__ W, const float* __restrict__ x,
                                float* __restrict__ out, int K, int N, int ldw)
{
    int n = blockIdx.x * blockDim.x + threadIdx.x;
    if (n >= N) return;
    float s = 0.f;
    for (int k = 0; k < K; ++k) s += x[k] * W[(size_t)k * ldw + n];
    out[n] = s;
}

// out[0] = critic_W.x + critic_b ; out[1..6] = actor_W @ x + actor_b
__global__ void final_heads_kernel(const float* __restrict__ x,
                                   const float* __restrict__ cW, const float* __restrict__ cb,
                                   const float* __restrict__ aW, const float* __restrict__ ab,
                                   float* __restrict__ out)
{
    int w = threadIdx.x >> 5;
    int lane = threadIdx.x & 31;
    if (w >= 7) return;
    const float* row = (w == 0) ? cW : (aW + (size_t)(w - 1) * 512);
    float s = 0.f;
    for (int k = lane; k < 512; k += 32) s += row[k] * x[k];
#pragma unroll
    for (int off = 16; off > 0; off >>= 1) s += __shfl_down_sync(0xffffffffu, s, off);
    if (lane == 0) out[w] = s + ((w == 0) ? cb[0] : ab[w - 1]);
}

// ---------------------------------------------------------------------------
// Launch
// ---------------------------------------------------------------------------
extern "C" void kernel_launch(void* const* d_in, const int* in_sizes, int n_in,
                              void* d_out, int out_size)
{
    const float* frames     = (const float*)d_in[0];   // [4,2048] -> 8192
    const float* scores     = (const float*)d_in[1];   // [1000]
    const float* word_embed = (const float*)d_in[2];   // [300]
    const float* all_embeds = (const float*)d_in[3];   // [4096,300]
    const float* adj        = (const float*)d_in[4];   // [4096,4096]
    const float* visual_W   = (const float*)d_in[5];   // [512,8192]
    const float* visual_b   = (const float*)d_in[6];
    const float* semantic_W = (const float*)d_in[7];   // [512,300]
    const float* semantic_b = (const float*)d_in[8];
    const float* score_W    = (const float*)d_in[9];   // [512,1000]
    const float* score_b    = (const float*)d_in[10];
    const float* gc1_W      = (const float*)d_in[11];  // [1024,1024] (in,out)
    const float* gc1_b      = (const float*)d_in[12];
    const float* gc2_W      = (const float*)d_in[13];  // [1024,1024]
    const float* gc2_b      = (const float*)d_in[14];
    const float* gc3_W      = (const float*)d_in[15];  // [1024,1]
    const float* gc3_b      = (const float*)d_in[16];  // [1]
    const float* gcn512_W   = (const float*)d_in[17];  // [512,4096]
    const float* gcn512_b   = (const float*)d_in[18];
    const float* hidden_W   = (const float*)d_in[19];  // [512,1536]
    const float* hidden_b   = (const float*)d_in[20];
    const float* critic_W   = (const float*)d_in[21];  // [1,512]
    const float* critic_b   = (const float*)d_in[22];
    const float* actor_W    = (const float*)d_in[23];  // [6,512]
    const float* actor_b    = (const float*)d_in[24];
    float* out = (float*)d_out;                        // [7] = [critic | actor(6)]

    float *em512, *t, *h, *scores512, *r, *v, *h3, *joint, *x;
    cudaGetSymbolAddress((void**)&em512,     g_em512);
    cudaGetSymbolAddress((void**)&t,         g_t);
    cudaGetSymbolAddress((void**)&h,         g_h);
    cudaGetSymbolAddress((void**)&scores512, g_scores512);
    cudaGetSymbolAddress((void**)&r,         g_r);
    cudaGetSymbolAddress((void**)&v,         g_v);
    cudaGetSymbolAddress((void**)&h3,        g_h3);
    cudaGetSymbolAddress((void**)&joint,     g_joint);
    cudaGetSymbolAddress((void**)&x,         g_x);

    // Small MLP branches (outputs written straight into their joint slots)
    gemv_kernel<<<512, 256>>>(visual_W,   frames,     visual_b,   joint + 0,    8192, 1, 0);
    gemv_kernel<<<512, 256>>>(semantic_W, word_embed, semantic_b, joint + 512,  300,  1, 0);
    gemv_kernel<<<512, 256>>>(score_W,    scores,     score_b,    scores512,    1000, 1, 0);

    // r[n] = scores512 @ gc1_W[:512, :]   (broadcast part of nodes @ gc1_W)
    gemv_xtw_kernel<<<4, 256>>>(gc1_W, scores512, r, 512, 1024, 1024);

    // em512 = relu(all_embeds @ semantic_W^T + semantic_b)   [4096,512]
    sgemm_kernel<true><<<dim3(512 / BN, N_OBJ / BM), 256>>>(
        all_embeds, semantic_W, em512, N_OBJ, 512, 300, semantic_b, 1);

    // t1 = em512 @ gc1_W[512:, :] + r          [4096,1024]
    sgemm_kernel<false><<<dim3(1024 / BN, N_OBJ / BM), 256>>>(
        em512, gc1_W + (size_t)512 * 1024, t, N_OBJ, 1024, 512, r, 0);

    // h1 = relu(adj @ t1 + gc1_b)
    sgemm_kernel<false><<<dim3(1024 / BN, N_OBJ / BM), 256>>>(
        adj, t, h, N_OBJ, 1024, N_OBJ, gc1_b, 1);

    // t2 = h1 @ gc2_W
    sgemm_kernel<false><<<dim3(1024 / BN, N_OBJ / BM), 256>>>(
        h, gc2_W, t, N_OBJ, 1024, 1024, nullptr, 0);

    // h2 = relu(adj @ t2 + gc2_b)
    sgemm_kernel<false><<<dim3(1024 / BN, N_OBJ / BM), 256>>>(
        adj, t, h, N_OBJ, 1024, N_OBJ, gc2_b, 1);

    // v = h2 @ gc3_W                          [4096]
    gemv_kernel<<<N_OBJ, 256>>>(h, gc3_W, nullptr, v, 1024, 0, 0);

    // h3 = relu(adj @ v + gc3_b)              [4096]
    gemv_kernel<<<N_OBJ, 256>>>(adj, v, gc3_b, h3, N_OBJ, 1, 1);

    // gcn512 = relu(gcn512_W @ h3 + b) -> joint[1024:1536]
    gemv_kernel<<<512, 256>>>(gcn512_W, h3, gcn512_b, joint + 1024, N_OBJ, 1, 0);

    // x = relu(hidden_W @ joint + hidden_b)
    gemv_kernel<<<512, 256>>>(hidden_W, joint, hidden_b, x, 1536, 1, 0);

    // heads
    final_heads_kernel<<<1, 256>>>(x, critic_W, critic_b, actor_W, actor_b, out);
}

// round 3
// speedup vs baseline: 2.3784x; 2.3784x over previous
#include <cuda_runtime.h>
#include <cuda_bf16.h>
#include <cstdint>
#include <cstddef>

#define N_OBJ 4096

// ===========================================================================
// Scratch (device globals; no dynamic allocation allowed)
// ===========================================================================
__device__ __nv_bfloat16 g_adjHi[(size_t)N_OBJ * N_OBJ];
__device__ __nv_bfloat16 g_adjLo[(size_t)N_OBJ * N_OBJ];
__device__ float         g_em512f[N_OBJ * 512];
__device__ __nv_bfloat16 g_emHi[N_OBJ * 512];
__device__ __nv_bfloat16 g_emLo[N_OBJ * 512];
__device__ __nv_bfloat16 g_gc1WtHi[1024 * 512];
__device__ __nv_bfloat16 g_gc1WtLo[1024 * 512];
__device__ __nv_bfloat16 g_gc2WtHi[1024 * 1024];
__device__ __nv_bfloat16 g_gc2WtLo[1024 * 1024];
__device__ __nv_bfloat16 g_tTHi[1024 * N_OBJ];   // t1^T then t2^T  [1024][4096]
__device__ __nv_bfloat16 g_tTLo[1024 * N_OBJ];
__device__ __nv_bfloat16 g_h1Hi[N_OBJ * 1024];   // h1 row-major splits
__device__ __nv_bfloat16 g_h1Lo[N_OBJ * 1024];
__device__ float         g_f32buf[N_OBJ * 1024]; // t1f -> t2f -> h2
__device__ float g_scores512[512];
__device__ float g_r[1024];
__device__ float g_v[N_OBJ];
__device__ float g_h3[N_OBJ];
__device__ float g_joint[1536];
__device__ float g_x[512];

// ===========================================================================
// PTX helpers (sm_80-class: cp.async / ldmatrix / mma.sync -- no 'a' features)
// ===========================================================================
__device__ __forceinline__ uint32_t smem_to_u32(const void* p) {
    uint32_t a;
    asm("{ .reg .u64 t; cvta.to.shared.u64 t, %1; cvt.u32.u64 %0, t; }" : "=r"(a) : "l"(p));
    return a;
}
__device__ __forceinline__ void cp16(uint32_t s, const void* g) {
    asm volatile("cp.async.cg.shared.global [%0], [%1], 16;" :: "r"(s), "l"(g));
}
__device__ __forceinline__ void cp_commit() { asm volatile("cp.async.commit_group;"); }
template <int NN> __device__ __forceinline__ void cp_wait() {
    asm volatile("cp.async.wait_group %0;" :: "n"(NN));
}
__device__ __forceinline__ void ldsm4(uint32_t* r, uint32_t a) {
    asm volatile("ldmatrix.sync.aligned.m8n8.x4.shared.b16 {%0,%1,%2,%3}, [%4];"
                 : "=r"(r[0]), "=r"(r[1]), "=r"(r[2]), "=r"(r[3]) : "r"(a));
}
__device__ __forceinline__ void ldsm2(uint32_t* r, uint32_t a) {
    asm volatile("ldmatrix.sync.aligned.m8n8.x2.shared.b16 {%0,%1}, [%2];"
                 : "=r"(r[0]), "=r"(r[1]) : "r"(a));
}
__device__ __forceinline__ void mma16816(float* c, const uint32_t* a, const uint32_t* b) {
    asm volatile("mma.sync.aligned.m16n8k16.row.col.f32.bf16.bf16.f32 "
                 "{%0,%1,%2,%3}, {%4,%5,%6,%7}, {%8,%9}, {%0,%1,%2,%3};"
                 : "+f"(c[0]), "+f"(c[1]), "+f"(c[2]), "+f"(c[3])
                 : "r"(a[0]), "r"(a[1]), "r"(a[2]), "r"(a[3]), "r"(b[0]), "r"(b[1]));
}

// ===========================================================================
// 3-term bf16-split tensor-core GEMM: C[M,N] = A @ B^T
//   A splits [M,K] row-major; B splits [N,K] row-major (K contiguous both)
//   C = Ahi@Bhi^T + Alo@Bhi^T + Ahi@Blo^T  (fp32 accumulators)
// CTA tile 128x128x32, 8 warps (2Mx4N), warp tile 64x32, double buffered.
// outmode 0: fp32 row-major outF; outmode 1: bf16 split row-major outHi/outLo
// ===========================================================================
#define TBM 128
#define TBN 128
#define TBK 32
#define PITCH 80                               // 64B payload + 16B pad
#define TILE_B (128 * PITCH)                   // 10240 bytes
#define ST_AHI 0
#define ST_ALO (1 * TILE_B)
#define ST_BHI (2 * TILE_B)
#define ST_BLO (3 * TILE_B)
#define STAGE_B (4 * TILE_B)                   // 40960
#define MMA_SMEM (2 * STAGE_B)                 // 81920

__device__ __forceinline__ void load_stage(
    uint32_t sbase, int buf, int kt,
    const __nv_bfloat16* __restrict__ Ahi, const __nv_bfloat16* __restrict__ Alo,
    const __nv_bfloat16* __restrict__ Bhi, const __nv_bfloat16* __restrict__ Blo,
    int m0, int n0, int K, int tid)
{
    const int k0 = kt * TBK;
#pragma unroll
    for (int t = 0; t < 8; ++t) {
        int idx = tid + t * 256;               // 0..2047
        int mat = idx >> 9;                    // 0..3
        int loc = idx & 511;
        int r = loc >> 2, ch = loc & 3;
        const __nv_bfloat16* src = (mat == 0) ? Ahi : (mat == 1) ? Alo : (mat == 2) ? Bhi : Blo;
        int row = ((mat < 2) ? m0 : n0) + r;
        uint32_t sa = sbase + (uint32_t)(buf * STAGE_B + mat * TILE_B + r * PITCH + ch * 16);
        cp16(sa, src + (size_t)row * K + k0 + ch * 8);
    }
    cp_commit();
}

__global__ __launch_bounds__(256, 2)
void mma_gemm3(const __nv_bfloat16* __restrict__ Ahi, const __nv_bfloat16* __restrict__ Alo,
               const __nv_bfloat16* __restrict__ Bhi, const __nv_bfloat16* __restrict__ Blo,
               int M, int N, int K,
               const float* __restrict__ addvec, int do_relu, int outmode,
               float* __restrict__ outF,
               __nv_bfloat16* __restrict__ outHi, __nv_bfloat16* __restrict__ outLo)
{
    extern __shared__ char sm[];
    const uint32_t sbase = smem_to_u32(sm);
    const int tid = threadIdx.x;
    const int wid = tid >> 5, lane = tid & 31;
    const int warp_m = wid >> 2, warp_n = wid & 3;   // 2 x 4
    const int m0 = blockIdx.y * TBM, n0 = blockIdx.x * TBN;

    float acc[4][4][4];
#pragma unroll
    for (int i = 0; i < 4; ++i)
#pragma unroll
        for (int j = 0; j < 4; ++j)
#pragma unroll
            for (int q = 0; q < 4; ++q) acc[i][j][q] = 0.f;

    const int KT = K / TBK;
    load_stage(sbase, 0, 0, Ahi, Alo, Bhi, Blo, m0, n0, K, tid);

    int buf = 0;
    for (int kt = 0; kt < KT; ++kt) {
        if (kt + 1 < KT) {
            load_stage(sbase, buf ^ 1, kt + 1, Ahi, Alo, Bhi, Blo, m0, n0, K, tid);
            cp_wait<1>();
        } else {
            cp_wait<0>();
        }
        __syncthreads();

        const uint32_t stg = sbase + (uint32_t)(buf * STAGE_B);
#pragma unroll
        for (int ks = 0; ks < 2; ++ks) {
            uint32_t aH[4][4], aL[4][4], bH[4][2], bL[4][2];
            const int arow = warp_m * 64 + (lane & 15);
            const int achunk = ks * 2 + (lane >> 4);
#pragma unroll
            for (int i = 0; i < 4; ++i) {
                uint32_t off = (uint32_t)((arow + i * 16) * PITCH + achunk * 16);
                ldsm4(aH[i], stg + ST_AHI + off);
                ldsm4(aL[i], stg + ST_ALO + off);
            }
            const int idxb = lane & 15;
            const int brow = warp_n * 32 + (idxb & 7);
            const int bchunk = ks * 2 + (idxb >> 3);
#pragma unroll
            for (int j = 0; j < 4; ++j) {
                uint32_t off = (uint32_t)((brow + j * 8) * PITCH + bchunk * 16);
                ldsm2(bH[j], stg + ST_BHI + off);
                ldsm2(bL[j], stg + ST_BLO + off);
            }
#pragma unroll
            for (int i = 0; i < 4; ++i)
#pragma unroll
                for (int j = 0; j < 4; ++j) {
                    mma16816(acc[i][j], aH[i], bH[j]);
                    mma16816(acc[i][j], aL[i], bH[j]);
                    mma16816(acc[i][j], aH[i], bL[j]);
                }
        }
        __syncthreads();
        buf ^= 1;
    }

    // epilogue
    const int mw = m0 + warp_m * 64;
    const int nw = n0 + warp_n * 32;
#pragma unroll
    for (int i = 0; i < 4; ++i) {
#pragma unroll
        for (int j = 0; j < 4; ++j) {
            int row = mw + i * 16 + (lane >> 2);
            int col = nw + j * 8 + (lane & 3) * 2;
            float v0 = acc[i][j][0], v1 = acc[i][j][1];
            float v2 = acc[i][j][2], v3 = acc[i][j][3];
            if (addvec) {
                float b0 = addvec[col], b1 = addvec[col + 1];
                v0 += b0; v1 += b1; v2 += b0; v3 += b1;
            }
            if (do_relu) {
                v0 = fmaxf(v0, 0.f); v1 = fmaxf(v1, 0.f);
                v2 = fmaxf(v2, 0.f); v3 = fmaxf(v3, 0.f);
            }
            if (outmode == 0) {
                *reinterpret_cast<float2*>(&outF[(size_t)row * N + col]) = make_float2(v0, v1);
                *reinterpret_cast<float2*>(&outF[(size_t)(row + 8) * N + col]) = make_float2(v2, v3);
            } else {
                __nv_bfloat16 h0 = __float2bfloat16(v0), h1 = __float2bfloat16(v1);
                __nv_bfloat16 h2 = __float2bfloat16(v2), h3 = __float2bfloat16(v3);
                __nv_bfloat16 l0 = __float2bfloat16(v0 - __bfloat162float(h0));
                __nv_bfloat16 l1 = __float2bfloat16(v1 - __bfloat162float(h1));
                __nv_bfloat16 l2 = __float2bfloat16(v2 - __bfloat162float(h2));
                __nv_bfloat16 l3 = __float2bfloat16(v3 - __bfloat162float(h3));
                *reinterpret_cast<__nv_bfloat162*>(&outHi[(size_t)row * N + col]) =
                    __halves2bfloat162(h0, h1);
                *reinterpret_cast<__nv_bfloat162*>(&outHi[(size_t)(row + 8) * N + col]) =
                    __halves2bfloat162(h2, h3);
                *reinterpret_cast<__nv_bfloat162*>(&outLo[(size_t)row * N + col]) =
                    __halves2bfloat162(l0, l1);
                *reinterpret_cast<__nv_bfloat162*>(&outLo[(size_t)(row + 8) * N + col]) =
                    __halves2bfloat162(l2, l3);
            }
        }
    }
}

// ===========================================================================
// fp32 SGEMM (for em512: K=300)
// ===========================================================================
#define BM 128
#define BN 128
#define BK 16
template <bool TRANSB>
__global__ __launch_bounds__(256, 2)
void sgemm_kernel(const float* __restrict__ A, const float* __restrict__ B,
                  float* __restrict__ C, int M, int N, int K,
                  const float* __restrict__ addvec, int do_relu)
{
    __shared__ float As[BK][BM + 4];
    __shared__ float Bs[BK][BN + 4];
    const int tid = threadIdx.x, tx = tid & 15, ty = tid >> 4;
    const int m0 = blockIdx.y * BM, n0 = blockIdx.x * BN;
    float acc[8][8];
#pragma unroll
    for (int i = 0; i < 8; ++i)
#pragma unroll
        for (int j = 0; j < 8; ++j) acc[i][j] = 0.f;

    for (int k0 = 0; k0 < K; k0 += BK) {
#pragma unroll
        for (int j = 0; j < 8; ++j) {
            int l = tid + j * 256, mm = l >> 4, kk = l & 15, gk = k0 + kk;
            As[kk][mm] = (gk < K) ? A[(size_t)(m0 + mm) * K + gk] : 0.f;
        }
        if (!TRANSB) {
#pragma unroll
            for (int j = 0; j < 8; ++j) {
                int l = tid + j * 256, kk = l >> 7, nn = l & 127, gk = k0 + kk;
                Bs[kk][nn] = (gk < K) ? B[(size_t)gk * N + (n0 + nn)] : 0.f;
            }
        } else {
#pragma unroll
            for (int j = 0; j < 8; ++j) {
                int l = tid + j * 256, nn = l >> 4, kk = l & 15, gk = k0 + kk;
                Bs[kk][nn] = (gk < K) ? B[(size_t)(n0 + nn) * K + gk] : 0.f;
            }
        }
        __syncthreads();
#pragma unroll
        for (int kk = 0; kk < BK; ++kk) {
            float ra[8], rb[8];
#pragma unroll
            for (int i = 0; i < 4; ++i) {
                ra[i] = As[kk][ty * 4 + i];  ra[4 + i] = As[kk][64 + ty * 4 + i];
                rb[i] = Bs[kk][tx * 4 + i];  rb[4 + i] = Bs[kk][64 + tx * 4 + i];
            }
#pragma unroll
            for (int i = 0; i < 8; ++i)
#pragma unroll
                for (int j = 0; j < 8; ++j) acc[i][j] += ra[i] * rb[j];
        }
        __syncthreads();
    }
#pragma unroll
    for (int i = 0; i < 8; ++i) {
        int mm = (i < 4) ? (ty * 4 + i) : (64 + ty * 4 + (i - 4));
#pragma unroll
        for (int j = 0; j < 8; ++j) {
            int nn = (j < 4) ? (tx * 4 + j) : (64 + tx * 4 + (j - 4));
            float v = acc[i][j];
            if (addvec) v += addvec[n0 + nn];
            if (do_relu) v = fmaxf(v, 0.f);
            C[(size_t)(m0 + mm) * N + (n0 + nn)] = v;
        }
    }
}

// ===========================================================================
// Pre/post kernels
// ===========================================================================
__global__ void split_kernel(const float* __restrict__ src,
                             __nv_bfloat16* __restrict__ hi, __nv_bfloat16* __restrict__ lo,
                             size_t n)
{
    size_t i = (size_t)blockIdx.x * 256 + threadIdx.x;
    if (i < n) {
        float v = src[i];
        __nv_bfloat16 h = __float2bfloat16(v);
        hi[i] = h;
        lo[i] = __float2bfloat16(v - __bfloat162float(h));
    }
}

// src [R,C] fp32 -> hi/lo [C,R] bf16
__global__ void splitT_kernel(const float* __restrict__ src,
                              __nv_bfloat16* __restrict__ hi, __nv_bfloat16* __restrict__ lo,
                              int R, int C)
{
    __shared__ float t[32][33];
    int c0 = blockIdx.x * 32, r0 = blockIdx.y * 32;
    for (int i = threadIdx.y; i < 32; i += 8)
        t[i][threadIdx.x] = src[(size_t)(r0 + i) * C + c0 + threadIdx.x];
    __syncthreads();
    for (int i = threadIdx.y; i < 32; i += 8) {
        float v = t[threadIdx.x][i];
        size_t o = (size_t)(c0 + i) * R + r0 + threadIdx.x;
        __nv_bfloat16 h = __float2bfloat16(v);
        hi[o] = h;
        lo[o] = __float2bfloat16(v - __bfloat162float(h));
    }
}

__global__ void gemv_kernel(const float* __restrict__ W, const float* __restrict__ x,
                            const float* __restrict__ b, float* __restrict__ out,
                            int K, int do_relu, int scalar_bias)
{
    const int row = blockIdx.x;
    const float* w = W + (size_t)row * K;
    float s = 0.f;
#pragma unroll 4
    for (int k = threadIdx.x; k < K; k += 256) s += w[k] * x[k];
    __shared__ float red[256];
    red[threadIdx.x] = s;
    __syncthreads();
#pragma unroll
    for (int off = 128; off > 0; off >>= 1) {
        if (threadIdx.x < off) red[threadIdx.x] += red[threadIdx.x + off];
        __syncthreads();
    }
    if (threadIdx.x == 0) {
        float v = red[0];
        if (b) v += scalar_bias ? b[0] : b[row];
        if (do_relu) v = fmaxf(v, 0.f);
        out[row] = v;
    }
}

// r[n] = sum_{k<512} x[k] * W[k*1024 + n]; grid 16 x 256 thr (64 n, 4 k-slices)
__global__ void r_kernel(const float* __restrict__ W, const float* __restrict__ x,
                         float* __restrict__ out)
{
    __shared__ float part[4][64];
    int nl = threadIdx.x & 63;
    int n = blockIdx.x * 64 + nl;
    int ks = threadIdx.x >> 6;
    float s = 0.f;
#pragma unroll 8
    for (int k = ks * 128; k < ks * 128 + 128; ++k) s += x[k] * W[(size_t)k * 1024 + n];
    part[ks][nl] = s;
    __syncthreads();
    if (threadIdx.x < 64)
        out[blockIdx.x * 64 + threadIdx.x] =
            part[0][threadIdx.x] + part[1][threadIdx.x] +
            part[2][threadIdx.x] + part[3][threadIdx.x];
}

__global__ void final_heads_kernel(const float* __restrict__ x,
                                   const float* __restrict__ cW, const float* __restrict__ cb,
                                   const float* __restrict__ aW, const float* __restrict__ ab,
                                   float* __restrict__ out)
{
    int w = threadIdx.x >> 5, lane = threadIdx.x & 31;
    if (w >= 7) return;
    const float* row = (w == 0) ? cW : (aW + (size_t)(w - 1) * 512);
    float s = 0.f;
    for (int k = lane; k < 512; k += 32) s += row[k] * x[k];
#pragma unroll
    for (int off = 16; off > 0; off >>= 1) s += __shfl_down_sync(0xffffffffu, s, off);
    if (lane == 0) out[w] = s + ((w == 0) ? cb[0] : ab[w - 1]);
}

// ===========================================================================
// Launch
// ===========================================================================
extern "C" void kernel_launch(void* const* d_in, const int* in_sizes, int n_in,
                              void* d_out, int out_size)
{
    const float* frames     = (const float*)d_in[0];
    const float* scores     = (const float*)d_in[1];
    const float* word_embed = (const float*)d_in[2];
    const float* all_embeds = (const float*)d_in[3];
    const float* adj        = (const float*)d_in[4];
    const float* visual_W   = (const float*)d_in[5];
    const float* visual_b   = (const float*)d_in[6];
    const float* semantic_W = (const float*)d_in[7];
    const float* semantic_b = (const float*)d_in[8];
    const float* score_W    = (const float*)d_in[9];
    const float* score_b    = (const float*)d_in[10];
    const float* gc1_W      = (const float*)d_in[11];
    const float* gc1_b      = (const float*)d_in[12];
    const float* gc2_W      = (const float*)d_in[13];
    const float* gc2_b      = (const float*)d_in[14];
    const float* gc3_W      = (const float*)d_in[15];
    const float* gc3_b      = (const float*)d_in[16];
    const float* gcn512_W   = (const float*)d_in[17];
    const float* gcn512_b   = (const float*)d_in[18];
    const float* hidden_W   = (const float*)d_in[19];
    const float* hidden_b   = (const float*)d_in[20];
    const float* critic_W   = (const float*)d_in[21];
    const float* critic_b   = (const float*)d_in[22];
    const float* actor_W    = (const float*)d_in[23];
    const float* actor_b    = (const float*)d_in[24];
    float* out = (float*)d_out;

    __nv_bfloat16 *adjHi, *adjLo, *emHi, *emLo, *gc1WtHi, *gc1WtLo, *gc2WtHi, *gc2WtLo;
    __nv_bfloat16 *tTHi, *tTLo, *h1Hi, *h1Lo;
    float *em512f, *f32buf, *scores512, *r, *v, *h3, *joint, *x;
    cudaGetSymbolAddress((void**)&adjHi, g_adjHi);
    cudaGetSymbolAddress((void**)&adjLo, g_adjLo);
    cudaGetSymbolAddress((void**)&em512f, g_em512f);
    cudaGetSymbolAddress((void**)&emHi, g_emHi);
    cudaGetSymbolAddress((void**)&emLo, g_emLo);
    cudaGetSymbolAddress((void**)&gc1WtHi, g_gc1WtHi);
    cudaGetSymbolAddress((void**)&gc1WtLo, g_gc1WtLo);
    cudaGetSymbolAddress((void**)&gc2WtHi, g_gc2WtHi);
    cudaGetSymbolAddress((void**)&gc2WtLo, g_gc2WtLo);
    cudaGetSymbolAddress((void**)&tTHi, g_tTHi);
    cudaGetSymbolAddress((void**)&tTLo, g_tTLo);
    cudaGetSymbolAddress((void**)&h1Hi, g_h1Hi);
    cudaGetSymbolAddress((void**)&h1Lo, g_h1Lo);
    cudaGetSymbolAddress((void**)&f32buf, g_f32buf);
    cudaGetSymbolAddress((void**)&scores512, g_scores512);
    cudaGetSymbolAddress((void**)&r, g_r);
    cudaGetSymbolAddress((void**)&v, g_v);
    cudaGetSymbolAddress((void**)&h3, g_h3);
    cudaGetSymbolAddress((void**)&joint, g_joint);
    cudaGetSymbolAddress((void**)&x, g_x);

    cudaFuncSetAttribute(mma_gemm3, cudaFuncAttributeMaxDynamicSharedMemorySize, MMA_SMEM);

    // --- small MLP branches ---
    gemv_kernel<<<512, 256>>>(visual_W,   frames,     visual_b,   joint + 0,   8192, 1, 0);
    gemv_kernel<<<512, 256>>>(semantic_W, word_embed, semantic_b, joint + 512, 300,  1, 0);
    gemv_kernel<<<512, 256>>>(score_W,    scores,     score_b,    scores512,   1000, 1, 0);
    r_kernel<<<16, 256>>>(gc1_W, scores512, r);

    // --- preprocessing splits ---
    split_kernel<<<(int)(((size_t)N_OBJ * N_OBJ + 255) / 256), 256>>>(
        adj, adjHi, adjLo, (size_t)N_OBJ * N_OBJ);
    splitT_kernel<<<dim3(1024 / 32, 512 / 32),  dim3(32, 8)>>>(
        gc1_W + (size_t)512 * 1024, gc1WtHi, gc1WtLo, 512, 1024);
    splitT_kernel<<<dim3(1024 / 32, 1024 / 32), dim3(32, 8)>>>(gc2_W, gc2WtHi, gc2WtLo, 1024, 1024);

    // em512 = relu(all_embeds @ semantic_W^T + b) (fp32, K=300), then split
    sgemm_kernel<true><<<dim3(512 / BN, N_OBJ / BM), 256>>>(
        all_embeds, semantic_W, em512f, N_OBJ, 512, 300, semantic_b, 1);
    split_kernel<<<(N_OBJ * 512 + 255) / 256, 256>>>(em512f, emHi, emLo, (size_t)N_OBJ * 512);

    // --- G1: t1 = em512 @ gc1W'^T + r  -> f32buf [4096,1024] ---
    mma_gemm3<<<dim3(1024 / TBN, N_OBJ / TBM), 256, MMA_SMEM>>>(
        emHi, emLo, gc1WtHi, gc1WtLo, N_OBJ, 1024, 512, r, 0, 0, f32buf, nullptr, nullptr);
    // t1^T splits [1024,4096]
    splitT_kernel<<<dim3(1024 / 32, N_OBJ / 32), dim3(32, 8)>>>(f32buf, tTHi, tTLo, N_OBJ, 1024);

    // --- G2: h1 = relu(adj @ t1 + gc1_b) -> h1 row-major splits ---
    mma_gemm3<<<dim3(1024 / TBN, N_OBJ / TBM), 256, MMA_SMEM>>>(
        adjHi, adjLo, tTHi, tTLo, N_OBJ, 1024, N_OBJ, gc1_b, 1, 1, nullptr, h1Hi, h1Lo);

    // --- G3: t2 = h1 @ gc2_W -> f32buf ---
    mma_gemm3<<<dim3(1024 / TBN, N_OBJ / TBM), 256, MMA_SMEM>>>(
        h1Hi, h1Lo, gc2WtHi, gc2WtLo, N_OBJ, 1024, 1024, nullptr, 0, 0, f32buf, nullptr, nullptr);
    // t2^T splits
    splitT_kernel<<<dim3(1024 / 32, N_OBJ / 32), dim3(32, 8)>>>(f32buf, tTHi, tTLo, N_OBJ, 1024);

    // --- G4: h2 = relu(adj @ t2 + gc2_b) -> f32buf row-major ---
    mma_gemm3<<<dim3(1024 / TBN, N_OBJ / TBM), 256, MMA_SMEM>>>(
        adjHi, adjLo, tTHi, tTLo, N_OBJ, 1024, N_OBJ, gc2_b, 1, 0, f32buf, nullptr, nullptr);

    // --- tail ---
    gemv_kernel<<<N_OBJ, 256>>>(f32buf, gc3_W, nullptr, v, 1024, 0, 0);       // v = h2 @ gc3_W
    gemv_kernel<<<N_OBJ, 256>>>(adj, v, gc3_b, h3, N_OBJ, 1, 1);              // h3 = relu(adj@v+b)
    gemv_kernel<<<512, 256>>>(gcn512_W, h3, gcn512_b, joint + 1024, N_OBJ, 1, 0);
    gemv_kernel<<<512, 256>>>(hidden_W, joint, hidden_b, x, 1536, 1, 0);
    final_heads_kernel<<<1, 256>>>(x, critic_W, critic_b, actor_W, actor_b, out);
}